// round 1
// baseline (speedup 1.0000x reference)
#include <cuda_runtime.h>
#include <cuda_bf16.h>

#define BATCH 4
#define CH    128
#define CINR  1024
#define NN    256
#define HH    120
#define WW    160
#define HWSZ  (HH*WW)

// ---------------- scratch (device globals; no allocations allowed) ----------
__device__ float g_depA[BATCH*2*CH*HWSZ];
__device__ float g_depB[BATCH*2*CH*HWSZ];
__device__ float g_imgA[BATCH*CH*HWSZ];
__device__ float g_relA[BATCH*CH*HWSZ];
__device__ float g_relB[BATCH*CH*HWSZ];
__device__ float g_hmid[BATCH*CH*NN];
__device__ float g_relmap[BATCH*CH*NN];

// ---------------- 1x1 conv == channel matmul --------------------------------
// out[b,o,n] = (relu)( sum_c Wm[o,c]*X[b,c,n] + bias[o] )
__global__ void mm_kernel(const float* __restrict__ X, const float* __restrict__ Wm,
                          const float* __restrict__ bias, float* __restrict__ out,
                          int Cin, int do_relu)
{
    const int o = blockIdx.x;          // 0..CH-1
    const int b = blockIdx.y;          // 0..BATCH-1
    const int n = threadIdx.x;         // 0..NN-1
    const float* xp = X + ((size_t)b * Cin) * NN + n;
    const float* wp = Wm + (size_t)o * Cin;
    float acc = bias[o];
    #pragma unroll 4
    for (int c = 0; c < Cin; ++c)
        acc = fmaf(wp[c], xp[(size_t)c * NN], acc);
    if (do_relu) acc = fmaxf(acc, 0.f);
    out[((size_t)b * CH + o) * NN + n] = acc;
}

// ---------------- box scatter of interpolated relation rows -----------------
// rel[b,c,y,x] = sum over valid boxes covering (y,x) of relmap[b,c,idx(y)]
// Per (b, y, half-of-channels) block: difference array along x in smem,
// then prefix-sum. Row stride 161 -> conflict-free banks and holds x2==160.
__global__ void scatter_kernel(const float* __restrict__ relmap,
                               const int* __restrict__ bbox,
                               float* __restrict__ rel)
{
    __shared__ float row[64 * 161];
    const int y  = blockIdx.x;
    const int b  = blockIdx.y;
    const int c0 = blockIdx.z * 64;
    const int c  = threadIdx.x;        // 0..63

    float* myrow = row + c * 161;
    #pragma unroll
    for (int x = 0; x < 161; ++x) myrow[x] = 0.f;

    const float* rm = relmap + ((size_t)(b * CH + c0 + c)) * NN;

    for (int n = 0; n < NN; ++n) {
        const int* bb = bbox + ((size_t)b * NN + n) * 8;
        int sx1 = bb[0] >> 1, sy1 = bb[1] >> 1, sx2 = bb[2] >> 1, sy2 = bb[3] >> 1;
        int ox1 = bb[4] >> 1, oy1 = bb[5] >> 1, ox2 = bb[6] >> 1, oy2 = bb[7] >> 1;
        int sh = sy2 - sy1, sw = sx2 - sx1;
        int oh = oy2 - oy1, ow = ox2 - ox1;
        if (!(sh >= 5 && sw >= 5 && oh >= 5 && ow >= 5)) continue;

        if (y >= sy1 && y < sy2) {
            int s = (y - sy1) * 256 / sh;  s = min(s, 255);
            float v = rm[s];
            myrow[sx1] += v;
            myrow[sx2] -= v;
        }
        if (y >= oy1 && y < oy2) {
            int s = (y - oy1) * 256 / oh;  s = min(s, 255);
            float v = rm[s];
            myrow[ox1] += v;
            myrow[ox2] -= v;
        }
    }

    float run = 0.f;
    float* op = rel + (((size_t)(b * CH + c0 + c)) * HH + y) * WW;
    #pragma unroll 4
    for (int x = 0; x < WW; ++x) { run += myrow[x]; op[x] = run; }
}

// ---------------- generic dual-input 3x3 SAME conv --------------------------
// out = (relu?)( base + scale*( conv(X1,W1)+b1 + conv(X2,W2)+b2 ) )
// Tile: 32(x) x 24(y), 192 threads, 4 px/thread in x, 16 Cout per block-z.
#define KO 16
#define CI 4
#define TW 32
#define TH 24
#define PX 4
#define NTHR 192   // (TW/PX)*TH

__global__ void __launch_bounds__(NTHR)
conv_kernel(float* __restrict__ out, const float* __restrict__ base,
            const float* __restrict__ X1, const float* __restrict__ W1, int C1,
            const float* __restrict__ X2, const float* __restrict__ W2, int C2,
            const float* __restrict__ B1, const float* __restrict__ B2,
            int Cout, float scale, int do_relu)
{
    const int tid = threadIdx.x;
    const int tx  = tid & 7;            // 0..7
    const int ty  = tid >> 3;           // 0..23
    const int x0  = blockIdx.x * TW;
    const int y0  = blockIdx.y * TH;
    const int nko = Cout / KO;
    const int b   = blockIdx.z / nko;
    const int ko0 = (blockIdx.z % nko) * KO;

    __shared__ float s_in[CI * 26 * 36];
    __shared__ float s_w[CI * KO * 9];

    float acc[KO][PX];
    #pragma unroll
    for (int k = 0; k < KO; ++k)
        #pragma unroll
        for (int j = 0; j < PX; ++j) acc[k][j] = 0.f;

    #pragma unroll 1
    for (int seg = 0; seg < 2; ++seg) {
        const float* X = seg ? X2 : X1;
        const float* W = seg ? W2 : W1;
        const int    C = seg ? C2 : C1;
        if (C == 0) continue;
        #pragma unroll 1
        for (int cc = 0; cc < C; cc += CI) {
            __syncthreads();
            // input halo tile: CI x 26 x 34 (row stride 36)
            for (int idx = tid; idx < CI * 26 * 34; idx += NTHR) {
                int ci = idx / (26 * 34);
                int r  = idx - ci * (26 * 34);
                int iy = r / 34, ix = r - iy * 34;
                int gy = y0 - 1 + iy, gx = x0 - 1 + ix;
                float v = 0.f;
                if ((unsigned)gy < (unsigned)HH && (unsigned)gx < (unsigned)WW)
                    v = X[(((size_t)b * C + (cc + ci)) * HH + gy) * WW + gx];
                s_in[(ci * 26 + iy) * 36 + ix] = v;
            }
            // weights: [ci][ko][9]
            for (int idx = tid; idx < KO * CI * 9; idx += NTHR) {
                int ci = idx / (KO * 9);
                int r  = idx - ci * (KO * 9);
                int ko = r / 9, t = r - ko * 9;
                s_w[(ci * KO + ko) * 9 + t] =
                    W[(((size_t)(ko0 + ko)) * C + (cc + ci)) * 9 + t];
            }
            __syncthreads();

            #pragma unroll
            for (int ci = 0; ci < CI; ++ci) {
                float iv0[6], iv1[6], iv2[6];
                const int ib = (ci * 26 + ty) * 36 + (tx << 2);
                #pragma unroll
                for (int m = 0; m < 6; ++m) {
                    iv0[m] = s_in[ib + m];
                    iv1[m] = s_in[ib + 36 + m];
                    iv2[m] = s_in[ib + 72 + m];
                }
                const float* wb = s_w + ci * (KO * 9);
                #pragma unroll
                for (int ko = 0; ko < KO; ++ko) {
                    const float* wp = wb + ko * 9;
                    const float w0 = wp[0], w1 = wp[1], w2 = wp[2];
                    const float w3 = wp[3], w4 = wp[4], w5 = wp[5];
                    const float w6 = wp[6], w7 = wp[7], w8 = wp[8];
                    #pragma unroll
                    for (int j = 0; j < PX; ++j) {
                        float a = acc[ko][j];
                        a = fmaf(w0, iv0[j],     a);
                        a = fmaf(w1, iv0[j + 1], a);
                        a = fmaf(w2, iv0[j + 2], a);
                        a = fmaf(w3, iv1[j],     a);
                        a = fmaf(w4, iv1[j + 1], a);
                        a = fmaf(w5, iv1[j + 2], a);
                        a = fmaf(w6, iv2[j],     a);
                        a = fmaf(w7, iv2[j + 1], a);
                        a = fmaf(w8, iv2[j + 2], a);
                        acc[ko][j] = a;
                    }
                }
            }
        }
    }

    // epilogue (H,W divide tiles exactly: 120=5*24, 160=5*32)
    const int y = y0 + ty;
    const int x = x0 + (tx << 2);
    #pragma unroll
    for (int ko = 0; ko < KO; ++ko) {
        const int c = ko0 + ko;
        const float bias = B1[c] + (B2 ? B2[c] : 0.f);
        const size_t o = (((size_t)b * Cout + c) * HH + y) * WW + x;
        float4 bs = base ? *(const float4*)(base + o) : make_float4(0.f, 0.f, 0.f, 0.f);
        float4 r;
        r.x = bs.x + scale * (acc[ko][0] + bias);
        r.y = bs.y + scale * (acc[ko][1] + bias);
        r.z = bs.z + scale * (acc[ko][2] + bias);
        r.w = bs.w + scale * (acc[ko][3] + bias);
        if (do_relu) {
            r.x = fmaxf(r.x, 0.f); r.y = fmaxf(r.y, 0.f);
            r.z = fmaxf(r.z, 0.f); r.w = fmaxf(r.w, 0.f);
        }
        *(float4*)(out + o) = r;
    }
}

static void conv_dual(float* out, const float* base,
                      const float* X1, const float* W1, int C1,
                      const float* X2, const float* W2, int C2,
                      const float* B1, const float* B2,
                      int Cout, float scale, int relu)
{
    dim3 g(WW / TW, HH / TH, BATCH * (Cout / KO));
    conv_kernel<<<g, NTHR>>>(out, base, X1, W1, C1, X2, W2, C2, B1, B2,
                             Cout, scale, relu);
}

// ---------------------------------------------------------------------------
extern "C" void kernel_launch(void* const* d_in, const int* in_sizes, int n_in,
                              void* d_out, int out_size)
{
    const float* img_in  = (const float*)d_in[0];
    const float* tf      = (const float*)d_in[1];
    const float* rw1     = (const float*)d_in[2];
    const float* rb1     = (const float*)d_in[3];
    const float* rw2     = (const float*)d_in[4];
    const float* rb2     = (const float*)d_in[5];
    const float* dmc_w   = (const float*)d_in[6];
    const float* dmc_b   = (const float*)d_in[7];
    const float* imc_w01 = (const float*)d_in[8];
    const float* imc_b01 = (const float*)d_in[9];
    const float* imc_w23 = (const float*)d_in[10];
    const float* imc_b23 = (const float*)d_in[11];
    const float* rmc_w01 = (const float*)d_in[12];
    const float* rmc_b01 = (const float*)d_in[13];
    const float* rmc_w23 = (const float*)d_in[14];
    const float* rmc_b23 = (const float*)d_in[15];
    const float* emb_w1  = (const float*)d_in[16];
    const float* emb_b1  = (const float*)d_in[17];
    const float* emb_w2  = (const float*)d_in[18];
    const float* emb_b2  = (const float*)d_in[19];
    const int*   bbox    = (const int*)d_in[20];
    float* out = (float*)d_out;

    float *depA, *depB, *imgA, *relA, *relB, *hmid, *relmap;
    cudaGetSymbolAddress((void**)&depA, g_depA);
    cudaGetSymbolAddress((void**)&depB, g_depB);
    cudaGetSymbolAddress((void**)&imgA, g_imgA);
    cudaGetSymbolAddress((void**)&relA, g_relA);
    cudaGetSymbolAddress((void**)&relB, g_relB);
    cudaGetSymbolAddress((void**)&hmid, g_hmid);
    cudaGetSymbolAddress((void**)&relmap, g_relmap);

    // 1) rel embedding: two channel matmuls
    mm_kernel<<<dim3(CH, BATCH), NN>>>(tf,   rw1, rb1, hmid,   CINR, 1);
    mm_kernel<<<dim3(CH, BATCH), NN>>>(hmid, rw2, rb2, relmap, CH,   0);

    // 2) scatter interpolated rows into rel map (writes every element)
    scatter_kernel<<<dim3(HH, BATCH, 2), 64>>>(relmap, bbox, relA);

    // 3) dep = concat(img, rel)  (channel-contiguous per batch -> 8 D2D copies)
    for (int b = 0; b < BATCH; ++b) {
        cudaMemcpyAsync(depA + ((size_t)b * 2 * CH) * HWSZ,
                        img_in + (size_t)b * CH * HWSZ,
                        sizeof(float) * CH * HWSZ, cudaMemcpyDeviceToDevice);
        cudaMemcpyAsync(depA + ((size_t)b * 2 * CH + CH) * HWSZ,
                        relA + (size_t)b * CH * HWSZ,
                        sizeof(float) * CH * HWSZ, cudaMemcpyDeviceToDevice);
    }

    const size_t WB = (size_t)2 * CH * CH * 9;  // 294912: ch->2ch / 2ch->ch blocks
    // 4) TriGraph iteration 0 (all three updates, pre-update reads)
    conv_dual(depB, depA, img_in, dmc_w + 0 * WB, CH,
                          relA,   dmc_w + 2 * WB, CH,
              dmc_b + 0 * 2 * CH, dmc_b + 2 * 2 * CH, 2 * CH, 0.5f, 1);
    conv_dual(imgA, img_in, depA, imc_w01, 2 * CH,
                            relA, imc_w23, CH,
              imc_b01, imc_b23, CH, 0.5f, 1);
    conv_dual(relB, relA, depA,   rmc_w01, 2 * CH,
                          img_in, rmc_w23, CH,
              rmc_b01, rmc_b23, CH, 0.5f, 1);

    // 5) TriGraph iteration 1: only dep feeds the output -> skip im/rm convs
    conv_dual(depA, depB, imgA, dmc_w + 1 * WB, CH,
                          relB, dmc_w + 3 * WB, CH,
              dmc_b + 1 * 2 * CH, dmc_b + 3 * 2 * CH, 2 * CH, 0.5f, 1);

    // 6) final embedding
    conv_dual(relA, nullptr, depA, emb_w1, 2 * CH,
              nullptr, nullptr, 0, emb_b1, nullptr, CH, 1.f, 1);
    conv_dual(out, nullptr, relA, emb_w2, CH,
              nullptr, nullptr, 0, emb_b2, nullptr, CH, 1.f, 0);
}

// round 3
// speedup vs baseline: 6.2712x; 6.2712x over previous
#include <cuda_runtime.h>
#include <cuda_bf16.h>
#include <cstdint>

#define BATCH 4
#define CH    128
#define CINR  1024
#define NN    256
#define HH    120
#define WW    160
#define HWSZ  (HH*WW)

#define KC    32
#define CTA_M 128
#define CTA_N 128

// ---------------- scratch (device globals; no allocations allowed) ----------
__device__ float g_depA[BATCH*2*CH*HWSZ];
__device__ float g_depB[BATCH*2*CH*HWSZ];
__device__ float g_imgA[BATCH*CH*HWSZ];
__device__ float g_relA[BATCH*CH*HWSZ];
__device__ float g_relB[BATCH*CH*HWSZ];
__device__ float g_hmid[BATCH*CH*NN];
__device__ float g_relmap[BATCH*CH*NN];

// ---------------- helpers ----------------------------------------------------
__device__ __forceinline__ float tf32r(float x){
    float y;
    asm("cvt.rna.tf32.f32 %0, %1;" : "=f"(y) : "f"(x));
    return y;
}
__device__ __forceinline__ void mma8(float* d, const float* a, const float* b){
    const uint32_t* A = (const uint32_t*)a;
    const uint32_t* B = (const uint32_t*)b;
    asm volatile(
        "mma.sync.aligned.m16n8k8.row.col.f32.tf32.tf32.f32 "
        "{%0,%1,%2,%3},{%4,%5,%6,%7},{%8,%9},{%0,%1,%2,%3};\n"
        : "+f"(d[0]), "+f"(d[1]), "+f"(d[2]), "+f"(d[3])
        : "r"(A[0]), "r"(A[1]), "r"(A[2]), "r"(A[3]), "r"(B[0]), "r"(B[1]));
}

// ---------------- 1x1 conv == channel matmul --------------------------------
__global__ void mm_kernel(const float* __restrict__ X, const float* __restrict__ Wm,
                          const float* __restrict__ bias, float* __restrict__ out,
                          int Cin, int do_relu)
{
    const int o = blockIdx.x;
    const int b = blockIdx.y;
    const int n = threadIdx.x;
    const float* xp = X + ((size_t)b * Cin) * NN + n;
    const float* wp = Wm + (size_t)o * Cin;
    float acc = bias[o];
    #pragma unroll 4
    for (int c = 0; c < Cin; ++c)
        acc = fmaf(wp[c], xp[(size_t)c * NN], acc);
    if (do_relu) acc = fmaxf(acc, 0.f);
    out[((size_t)b * CH + o) * NN + n] = acc;
}

// ---------------- box scatter of interpolated relation rows -----------------
__global__ void scatter_kernel(const float* __restrict__ relmap,
                               const int* __restrict__ bbox,
                               float* __restrict__ rel)
{
    __shared__ float row[64 * 161];
    const int y  = blockIdx.x;
    const int b  = blockIdx.y;
    const int c0 = blockIdx.z * 64;
    const int c  = threadIdx.x;

    float* myrow = row + c * 161;
    #pragma unroll
    for (int x = 0; x < 161; ++x) myrow[x] = 0.f;

    const float* rm = relmap + ((size_t)(b * CH + c0 + c)) * NN;

    for (int n = 0; n < NN; ++n) {
        const int* bb = bbox + ((size_t)b * NN + n) * 8;
        int sx1 = bb[0] >> 1, sy1 = bb[1] >> 1, sx2 = bb[2] >> 1, sy2 = bb[3] >> 1;
        int ox1 = bb[4] >> 1, oy1 = bb[5] >> 1, ox2 = bb[6] >> 1, oy2 = bb[7] >> 1;
        int sh = sy2 - sy1, sw = sx2 - sx1;
        int oh = oy2 - oy1, ow = ox2 - ox1;
        if (!(sh >= 5 && sw >= 5 && oh >= 5 && ow >= 5)) continue;

        if (y >= sy1 && y < sy2) {
            int s = (y - sy1) * 256 / sh;  s = min(s, 255);
            float v = rm[s];
            myrow[sx1] += v;
            myrow[sx2] -= v;
        }
        if (y >= oy1 && y < oy2) {
            int s = (y - oy1) * 256 / oh;  s = min(s, 255);
            float v = rm[s];
            myrow[ox1] += v;
            myrow[ox2] -= v;
        }
    }

    float run = 0.f;
    float* op = rel + (((size_t)(b * CH + c0 + c)) * HH + y) * WW;
    #pragma unroll 4
    for (int x = 0; x < WW; ++x) { run += myrow[x]; op[x] = run; }
}

// ============ tf32 mma.sync implicit-GEMM dual-input 3x3 SAME conv ==========
// out[b, co, pix] = relu?( base + scale*(conv(X1,W1)+conv(X2,W2)+bias) )
// A: weights [CTA_M][KC] (row-major m x k), B: im2col [CTA_N][KC] (k-contig per n).
// Smem rows padded to 36 words; within each 8-k group words are permuted
// pos = (k&3)*2 + ((k>>2)&1) so fragment loads are single LDS.64.
__global__ void __launch_bounds__(128, 2)
conv_mma(float* __restrict__ outp, const float* __restrict__ base,
         const float* __restrict__ X1, const float* __restrict__ W1, int C1,
         const float* __restrict__ X2, const float* __restrict__ W2, int C2,
         const float* __restrict__ B1, const float* __restrict__ B2,
         int Cout, float scale, int do_relu)
{
    __shared__ float sA[CTA_M * 36];
    __shared__ float sB[CTA_N * 36];

    const int tid  = threadIdx.x;
    const int lane = tid & 31;
    const int wid  = tid >> 5;
    const int g    = lane >> 2;
    const int c    = lane & 3;
    const int wm   = wid >> 1;      // 0..1
    const int wn   = wid & 1;       // 0..1

    const int n0  = blockIdx.x * CTA_N;
    const int co0 = blockIdx.y * CTA_M;
    const int b   = blockIdx.z;

    // B staging roles: 8 k-quads x 16 n-lanes
    const int k4 = tid >> 4;
    const int nb = tid & 15;
    const int wb = (k4 >> 1) * 8 + (k4 & 1);   // smem word base for this k-quad

    int nfix[8];
    int vmask[8];
    #pragma unroll
    for (int j = 0; j < 8; ++j) {
        const int n = n0 + nb + 16 * j;
        const int y = n / WW;
        const int x = n - y * WW;
        nfix[j]  = n - (WW + 1);
        vmask[j] = (y > 0) | ((y < HH - 1) << 1) | ((x > 0) << 2) | ((x < WW - 1) << 3);
    }

    float acc[4][8][4];
    #pragma unroll
    for (int mi = 0; mi < 4; ++mi)
        #pragma unroll
        for (int nj = 0; nj < 8; ++nj)
            #pragma unroll
            for (int t = 0; t < 4; ++t) acc[mi][nj][t] = 0.f;

    #pragma unroll 1
    for (int seg = 0; seg < 2; ++seg) {
        const float* X = seg ? X2 : X1;
        const float* W = seg ? W2 : W1;
        const int    C = seg ? C2 : C1;
        if (C == 0) continue;
        const float* Xb = X + (size_t)b * C * HWSZ;
        const int K   = C * 9;
        const int nch = K >> 5;

        #pragma unroll 1
        for (int cc = 0; cc < nch; ++cc) {
            const int k0 = cc * KC;
            __syncthreads();

            // ---- stage A: 128 co x 32 k ----
            #pragma unroll
            for (int j = 0; j < 8; ++j) {
                const int e  = tid + j * 128;
                const int co = e >> 3;
                const int kq = e & 7;
                const float4 v = *(const float4*)(W + (size_t)(co0 + co) * K + k0 + kq * 4);
                float* d = &sA[co * 36 + (kq >> 1) * 8 + (kq & 1)];
                d[0] = tf32r(v.x); d[2] = tf32r(v.y);
                d[4] = tf32r(v.z); d[6] = tf32r(v.w);
            }

            // ---- stage B: 128 n x 32 k (im2col gather) ----
            int kb[4], req[4];
            #pragma unroll
            for (int i = 0; i < 4; ++i) {
                const int k   = k0 + k4 * 4 + i;
                const int ci  = k / 9;
                const int tap = k - ci * 9;
                const int dy  = tap / 3;
                const int dx  = tap - dy * 3;
                kb[i]  = ci * HWSZ + dy * WW + dx;
                req[i] = (dy == 0 ? 1 : (dy == 2 ? 2 : 0)) |
                         (dx == 0 ? 4 : (dx == 2 ? 8 : 0));
            }
            #pragma unroll
            for (int j = 0; j < 8; ++j) {
                float* dst = &sB[(nb + 16 * j) * 36 + wb];
                #pragma unroll
                for (int i = 0; i < 4; ++i) {
                    float v = 0.f;
                    if ((vmask[j] & req[i]) == req[i]) v = Xb[kb[i] + nfix[j]];
                    dst[2 * i] = tf32r(v);
                }
            }
            __syncthreads();

            // ---- MMA over 4 k-slices ----
            #pragma unroll
            for (int s = 0; s < 4; ++s) {
                float af[4][4];
                float bf[8][2];
                #pragma unroll
                for (int mi = 0; mi < 4; ++mi) {
                    const int r = wm * 64 + mi * 16 + g;
                    const float2 p = *(const float2*)&sA[r * 36 + s * 8 + 2 * c];
                    const float2 q = *(const float2*)&sA[(r + 8) * 36 + s * 8 + 2 * c];
                    af[mi][0] = p.x; af[mi][1] = q.x;
                    af[mi][2] = p.y; af[mi][3] = q.y;
                }
                #pragma unroll
                for (int nj = 0; nj < 8; ++nj) {
                    const int r = wn * 64 + nj * 8 + g;
                    const float2 p = *(const float2*)&sB[r * 36 + s * 8 + 2 * c];
                    bf[nj][0] = p.x; bf[nj][1] = p.y;
                }
                #pragma unroll
                for (int mi = 0; mi < 4; ++mi)
                    #pragma unroll
                    for (int nj = 0; nj < 8; ++nj)
                        mma8(acc[mi][nj], af[mi], bf[nj]);
            }
        }
    }

    // ---- epilogue ----
    #pragma unroll
    for (int mi = 0; mi < 4; ++mi) {
        const int coa = co0 + wm * 64 + mi * 16 + g;
        const int cob = coa + 8;
        const float ba = B1[coa] + (B2 ? B2[coa] : 0.f);
        const float bb = B1[cob] + (B2 ? B2[cob] : 0.f);
        #pragma unroll
        for (int nj = 0; nj < 8; ++nj) {
            const int pix = n0 + wn * 64 + nj * 8 + 2 * c;
            const size_t oa = ((size_t)(b * Cout + coa)) * HWSZ + pix;
            const size_t ob = ((size_t)(b * Cout + cob)) * HWSZ + pix;
            float2 r0, r1;
            r0.x = acc[mi][nj][0] + ba;  r0.y = acc[mi][nj][1] + ba;
            r1.x = acc[mi][nj][2] + bb;  r1.y = acc[mi][nj][3] + bb;
            if (base) {
                const float2 s0 = *(const float2*)(base + oa);
                const float2 s1 = *(const float2*)(base + ob);
                r0.x = fmaf(scale, r0.x, s0.x);  r0.y = fmaf(scale, r0.y, s0.y);
                r1.x = fmaf(scale, r1.x, s1.x);  r1.y = fmaf(scale, r1.y, s1.y);
            } else {
                r0.x *= scale; r0.y *= scale;
                r1.x *= scale; r1.y *= scale;
            }
            if (do_relu) {
                r0.x = fmaxf(r0.x, 0.f); r0.y = fmaxf(r0.y, 0.f);
                r1.x = fmaxf(r1.x, 0.f); r1.y = fmaxf(r1.y, 0.f);
            }
            *(float2*)(outp + oa) = r0;
            *(float2*)(outp + ob) = r1;
        }
    }
}

static void conv_dual(float* out, const float* base,
                      const float* X1, const float* W1, int C1,
                      const float* X2, const float* W2, int C2,
                      const float* B1, const float* B2,
                      int Cout, float scale, int relu)
{
    dim3 g(HWSZ / CTA_N, Cout / CTA_M, BATCH);
    conv_mma<<<g, 128>>>(out, base, X1, W1, C1, X2, W2, C2, B1, B2,
                         Cout, scale, relu);
}

// ---------------------------------------------------------------------------
extern "C" void kernel_launch(void* const* d_in, const int* in_sizes, int n_in,
                              void* d_out, int out_size)
{
    const float* img_in  = (const float*)d_in[0];
    const float* tf      = (const float*)d_in[1];
    const float* rw1     = (const float*)d_in[2];
    const float* rb1     = (const float*)d_in[3];
    const float* rw2     = (const float*)d_in[4];
    const float* rb2     = (const float*)d_in[5];
    const float* dmc_w   = (const float*)d_in[6];
    const float* dmc_b   = (const float*)d_in[7];
    const float* imc_w01 = (const float*)d_in[8];
    const float* imc_b01 = (const float*)d_in[9];
    const float* imc_w23 = (const float*)d_in[10];
    const float* imc_b23 = (const float*)d_in[11];
    const float* rmc_w01 = (const float*)d_in[12];
    const float* rmc_b01 = (const float*)d_in[13];
    const float* rmc_w23 = (const float*)d_in[14];
    const float* rmc_b23 = (const float*)d_in[15];
    const float* emb_w1  = (const float*)d_in[16];
    const float* emb_b1  = (const float*)d_in[17];
    const float* emb_w2  = (const float*)d_in[18];
    const float* emb_b2  = (const float*)d_in[19];
    const int*   bbox    = (const int*)d_in[20];
    float* out = (float*)d_out;

    float *depA, *depB, *imgA, *relA, *relB, *hmid, *relmap;
    cudaGetSymbolAddress((void**)&depA, g_depA);
    cudaGetSymbolAddress((void**)&depB, g_depB);
    cudaGetSymbolAddress((void**)&imgA, g_imgA);
    cudaGetSymbolAddress((void**)&relA, g_relA);
    cudaGetSymbolAddress((void**)&relB, g_relB);
    cudaGetSymbolAddress((void**)&hmid, g_hmid);
    cudaGetSymbolAddress((void**)&relmap, g_relmap);

    // 1) rel embedding: two channel matmuls
    mm_kernel<<<dim3(CH, BATCH), NN>>>(tf,   rw1, rb1, hmid,   CINR, 1);
    mm_kernel<<<dim3(CH, BATCH), NN>>>(hmid, rw2, rb2, relmap, CH,   0);

    // 2) scatter interpolated rows into rel map (writes every element)
    scatter_kernel<<<dim3(HH, BATCH, 2), 64>>>(relmap, bbox, relA);

    // 3) dep = concat(img, rel)
    for (int b = 0; b < BATCH; ++b) {
        cudaMemcpyAsync(depA + ((size_t)b * 2 * CH) * HWSZ,
                        img_in + (size_t)b * CH * HWSZ,
                        sizeof(float) * CH * HWSZ, cudaMemcpyDeviceToDevice);
        cudaMemcpyAsync(depA + ((size_t)b * 2 * CH + CH) * HWSZ,
                        relA + (size_t)b * CH * HWSZ,
                        sizeof(float) * CH * HWSZ, cudaMemcpyDeviceToDevice);
    }

    const size_t WB = (size_t)2 * CH * CH * 9;
    // 4) TriGraph iteration 0
    conv_dual(depB, depA, img_in, dmc_w + 0 * WB, CH,
                          relA,   dmc_w + 2 * WB, CH,
              dmc_b + 0 * 2 * CH, dmc_b + 2 * 2 * CH, 2 * CH, 0.5f, 1);
    conv_dual(imgA, img_in, depA, imc_w01, 2 * CH,
                            relA, imc_w23, CH,
              imc_b01, imc_b23, CH, 0.5f, 1);
    conv_dual(relB, relA, depA,   rmc_w01, 2 * CH,
                          img_in, rmc_w23, CH,
              rmc_b01, rmc_b23, CH, 0.5f, 1);

    // 5) TriGraph iteration 1: only dep feeds the output
    conv_dual(depA, depB, imgA, dmc_w + 1 * WB, CH,
                          relB, dmc_w + 3 * WB, CH,
              dmc_b + 1 * 2 * CH, dmc_b + 3 * 2 * CH, 2 * CH, 0.5f, 1);

    // 6) final embedding
    conv_dual(relA, nullptr, depA, emb_w1, 2 * CH,
              nullptr, nullptr, 0, emb_b1, nullptr, CH, 1.f, 1);
    conv_dual(out, nullptr, relA, emb_w2, CH,
              nullptr, nullptr, 0, emb_b2, nullptr, CH, 1.f, 0);
}

// round 4
// speedup vs baseline: 6.3913x; 1.0191x over previous
#include <cuda_runtime.h>
#include <cuda_bf16.h>
#include <cstdint>

#define BATCH 4
#define CH    128
#define CINR  1024
#define NN    256
#define HH    120
#define WW    160
#define HWSZ  (HH*WW)

#define KC    32
#define CTA_M 128
#define CTA_N 128
#define SROW  40            // smem row stride in words (conflict-free phases)

// ---------------- scratch (device globals; no allocations allowed) ----------
__device__ float g_depA[BATCH*2*CH*HWSZ];
__device__ float g_depB[BATCH*2*CH*HWSZ];
__device__ float g_imgA[BATCH*CH*HWSZ];
__device__ float g_relA[BATCH*CH*HWSZ];
__device__ float g_relB[BATCH*CH*HWSZ];
__device__ float g_hmid[BATCH*CH*NN];
__device__ float g_relmap[BATCH*CH*NN];
__device__ float g_wpack[2506752];

// pack-section offsets (floats)
#define WP1 0
#define WP2 589824
#define WP3 1032192
#define WP4 1474560
#define WP5 2064384
#define WP6 2359296

// ---------------- helpers ----------------------------------------------------
__device__ __forceinline__ float tf32r(float x){
    float y;
    asm("cvt.rna.tf32.f32 %0, %1;" : "=f"(y) : "f"(x));
    return y;
}
__device__ __forceinline__ void mma8(float* d, const float* a, const float* b){
    const uint32_t* A = (const uint32_t*)a;
    const uint32_t* B = (const uint32_t*)b;
    asm volatile(
        "mma.sync.aligned.m16n8k8.row.col.f32.tf32.tf32.f32 "
        "{%0,%1,%2,%3},{%4,%5,%6,%7},{%8,%9},{%0,%1,%2,%3};\n"
        : "+f"(d[0]), "+f"(d[1]), "+f"(d[2]), "+f"(d[3])
        : "r"(A[0]), "r"(A[1]), "r"(A[2]), "r"(A[3]), "r"(B[0]), "r"(B[1]));
}

// ---------------- weight pack: tf32 cvt + MMA column permutation ------------
// dst[co][cb + col] where col = s*8 + 2*(ks&3) + (ks>>2), ks = k&7, s=(k>>3)&3
__global__ void pack_kernel(float* __restrict__ dst,
                            const float* __restrict__ W1, int K1,
                            const float* __restrict__ W2, int K2,
                            int Cout)
{
    const int Kt = K1 + K2;
    const int total = Cout * Kt;
    for (int idx = blockIdx.x * blockDim.x + threadIdx.x; idx < total;
         idx += gridDim.x * blockDim.x) {
        const int co = idx / Kt;
        const int kg = idx - co * Kt;
        float v = (kg < K1) ? W1[(size_t)co * K1 + kg]
                            : W2[(size_t)co * K2 + (kg - K1)];
        const int cb  = kg & ~31;
        const int w   = kg & 31;
        const int s   = w >> 3;
        const int ks  = w & 7;
        const int col = s * 8 + 2 * (ks & 3) + (ks >> 2);
        dst[(size_t)co * Kt + cb + col] = tf32r(v);
    }
}

// ---------------- 1x1 conv == channel matmul --------------------------------
__global__ void mm_kernel(const float* __restrict__ X, const float* __restrict__ Wm,
                          const float* __restrict__ bias, float* __restrict__ out,
                          int Cin, int do_relu)
{
    const int o = blockIdx.x;
    const int b = blockIdx.y;
    const int n = threadIdx.x;
    const float* xp = X + ((size_t)b * Cin) * NN + n;
    const float* wp = Wm + (size_t)o * Cin;
    float acc = bias[o];
    #pragma unroll 4
    for (int c = 0; c < Cin; ++c)
        acc = fmaf(wp[c], xp[(size_t)c * NN], acc);
    if (do_relu) acc = fmaxf(acc, 0.f);
    out[((size_t)b * CH + o) * NN + n] = acc;
}

// ---------------- box scatter of interpolated relation rows -----------------
__global__ void scatter_kernel(const float* __restrict__ relmap,
                               const int* __restrict__ bbox,
                               float* __restrict__ rel)
{
    __shared__ float row[64 * 161];
    const int y  = blockIdx.x;
    const int b  = blockIdx.y;
    const int c0 = blockIdx.z * 64;
    const int c  = threadIdx.x;

    float* myrow = row + c * 161;
    #pragma unroll
    for (int x = 0; x < 161; ++x) myrow[x] = 0.f;

    const float* rm = relmap + ((size_t)(b * CH + c0 + c)) * NN;

    for (int n = 0; n < NN; ++n) {
        const int* bb = bbox + ((size_t)b * NN + n) * 8;
        int sx1 = bb[0] >> 1, sy1 = bb[1] >> 1, sx2 = bb[2] >> 1, sy2 = bb[3] >> 1;
        int ox1 = bb[4] >> 1, oy1 = bb[5] >> 1, ox2 = bb[6] >> 1, oy2 = bb[7] >> 1;
        int sh = sy2 - sy1, sw = sx2 - sx1;
        int oh = oy2 - oy1, ow = ox2 - ox1;
        if (!(sh >= 5 && sw >= 5 && oh >= 5 && ow >= 5)) continue;

        if (y >= sy1 && y < sy2) {
            int s = (y - sy1) * 256 / sh;  s = min(s, 255);
            float v = rm[s];
            myrow[sx1] += v;
            myrow[sx2] -= v;
        }
        if (y >= oy1 && y < oy2) {
            int s = (y - oy1) * 256 / oh;  s = min(s, 255);
            float v = rm[s];
            myrow[ox1] += v;
            myrow[ox2] -= v;
        }
    }

    float run = 0.f;
    float* op = rel + (((size_t)(b * CH + c0 + c)) * HH + y) * WW;
    #pragma unroll 4
    for (int x = 0; x < WW; ++x) { run += myrow[x]; op[x] = run; }
}

// ============ tf32 mma.sync implicit-GEMM dual-input 3x3 SAME conv ==========
// Weights come pre-converted + pre-permuted (wp, packed over both segments).
__global__ void __launch_bounds__(128, 2)
conv_mma(float* __restrict__ outp, const float* __restrict__ base,
         const float* __restrict__ X1, int C1,
         const float* __restrict__ X2, int C2,
         const float* __restrict__ wp,
         const float* __restrict__ B1, const float* __restrict__ B2,
         int Cout, float scale, int do_relu)
{
    __shared__ float sA[CTA_M * SROW];
    __shared__ float sB[CTA_N * SROW];

    const int tid  = threadIdx.x;
    const int lane = tid & 31;
    const int wid  = tid >> 5;
    const int g    = lane >> 2;
    const int c    = lane & 3;
    const int wm   = wid >> 1;      // 0..1
    const int wn   = wid & 1;       // 0..1

    const int n0  = blockIdx.x * CTA_N;
    const int co0 = blockIdx.y * CTA_M;
    const int b   = blockIdx.z;
    const int Kt  = (C1 + C2) * 9;

    // B staging roles: thread handles quad q (4 k's) x 8 pixels
    const int k4 = tid >> 4;            // 0..7
    const int nb = tid & 15;            // 0..15
    const int q  = (k4 + nb) & 7;       // conflict-free STS.128 quads
    int kq[4];
    {
        const int s = q >> 1;
        #pragma unroll
        for (int m = 0; m < 4; ++m) {
            const int cs = (q & 1) * 4 + m;
            kq[m] = s * 8 + (cs >> 1) + 4 * (cs & 1);
        }
    }

    int nfix[8];
    int vmask[8];
    #pragma unroll
    for (int j = 0; j < 8; ++j) {
        const int n = n0 + nb + 16 * j;
        const int y = n / WW;
        const int x = n - y * WW;
        nfix[j]  = n - (WW + 1);
        vmask[j] = (y > 0) | ((y < HH - 1) << 1) | ((x > 0) << 2) | ((x < WW - 1) << 3);
    }

    float acc[4][8][4];
    #pragma unroll
    for (int mi = 0; mi < 4; ++mi)
        #pragma unroll
        for (int nj = 0; nj < 8; ++nj)
            #pragma unroll
            for (int t = 0; t < 4; ++t) acc[mi][nj][t] = 0.f;

    int gk = 0;   // global chunk index (into packed weight columns)
    #pragma unroll 1
    for (int seg = 0; seg < 2; ++seg) {
        const float* X = seg ? X2 : X1;
        const int    C = seg ? C2 : C1;
        if (C == 0) continue;
        const float* Xb = X + (size_t)b * C * HWSZ;
        const int nch = (C * 9) >> 5;

        #pragma unroll 1
        for (int cc = 0; cc < nch; ++cc, ++gk) {
            const int k0 = cc * KC;          // within-segment k base
            const int wcol0 = gk * KC;       // packed weight column base
            __syncthreads();

            // ---- stage A: straight vector copy of packed weights ----
            #pragma unroll
            for (int j = 0; j < 8; ++j) {
                const int e  = tid + j * 128;
                const int co = e >> 3;
                const int qq = e & 7;
                const float4 v = *(const float4*)(wp + (size_t)(co0 + co) * Kt
                                                  + wcol0 + qq * 4);
                *(float4*)&sA[co * SROW + qq * 4] = v;
            }

            // ---- stage B: im2col gather, one STS.128 per pixel ----
            int kb[4], req[4];
            #pragma unroll
            for (int i = 0; i < 4; ++i) {
                const int k   = k0 + kq[i];
                const int ci  = k / 9;
                const int tap = k - ci * 9;
                const int dy  = tap / 3;
                const int dx  = tap - dy * 3;
                kb[i]  = ci * HWSZ + dy * WW + dx;
                req[i] = (dy == 0 ? 1 : (dy == 2 ? 2 : 0)) |
                         (dx == 0 ? 4 : (dx == 2 ? 8 : 0));
            }
            #pragma unroll
            for (int j = 0; j < 8; ++j) {
                float4 v;
                float* pv = (float*)&v;
                #pragma unroll
                for (int i = 0; i < 4; ++i) {
                    float t = 0.f;
                    if ((vmask[j] & req[i]) == req[i]) t = Xb[kb[i] + nfix[j]];
                    pv[i] = tf32r(t);
                }
                *(float4*)&sB[(nb + 16 * j) * SROW + q * 4] = v;
            }
            __syncthreads();

            // ---- MMA over 4 k-slices ----
            #pragma unroll
            for (int s = 0; s < 4; ++s) {
                float af[4][4];
                float bf[8][2];
                #pragma unroll
                for (int mi = 0; mi < 4; ++mi) {
                    const int r = wm * 64 + mi * 16 + g;
                    const float2 p = *(const float2*)&sA[r * SROW + s * 8 + 2 * c];
                    const float2 qd = *(const float2*)&sA[(r + 8) * SROW + s * 8 + 2 * c];
                    af[mi][0] = p.x;  af[mi][1] = qd.x;
                    af[mi][2] = p.y;  af[mi][3] = qd.y;
                }
                #pragma unroll
                for (int nj = 0; nj < 8; ++nj) {
                    const int r = wn * 64 + nj * 8 + g;
                    const float2 p = *(const float2*)&sB[r * SROW + s * 8 + 2 * c];
                    bf[nj][0] = p.x;  bf[nj][1] = p.y;
                }
                #pragma unroll
                for (int mi = 0; mi < 4; ++mi)
                    #pragma unroll
                    for (int nj = 0; nj < 8; ++nj)
                        mma8(acc[mi][nj], af[mi], bf[nj]);
            }
        }
    }

    // ---- epilogue ----
    #pragma unroll
    for (int mi = 0; mi < 4; ++mi) {
        const int coa = co0 + wm * 64 + mi * 16 + g;
        const int cob = coa + 8;
        const float ba = B1[coa] + (B2 ? B2[coa] : 0.f);
        const float bb = B1[cob] + (B2 ? B2[cob] : 0.f);
        #pragma unroll
        for (int nj = 0; nj < 8; ++nj) {
            const int pix = n0 + wn * 64 + nj * 8 + 2 * c;
            const size_t oa = ((size_t)(b * Cout + coa)) * HWSZ + pix;
            const size_t ob = ((size_t)(b * Cout + cob)) * HWSZ + pix;
            float2 r0, r1;
            r0.x = acc[mi][nj][0] + ba;  r0.y = acc[mi][nj][1] + ba;
            r1.x = acc[mi][nj][2] + bb;  r1.y = acc[mi][nj][3] + bb;
            if (base) {
                const float2 s0 = *(const float2*)(base + oa);
                const float2 s1 = *(const float2*)(base + ob);
                r0.x = fmaf(scale, r0.x, s0.x);  r0.y = fmaf(scale, r0.y, s0.y);
                r1.x = fmaf(scale, r1.x, s1.x);  r1.y = fmaf(scale, r1.y, s1.y);
            } else {
                r0.x *= scale; r0.y *= scale;
                r1.x *= scale; r1.y *= scale;
            }
            if (do_relu) {
                r0.x = fmaxf(r0.x, 0.f); r0.y = fmaxf(r0.y, 0.f);
                r1.x = fmaxf(r1.x, 0.f); r1.y = fmaxf(r1.y, 0.f);
            }
            *(float2*)(outp + oa) = r0;
            *(float2*)(outp + ob) = r1;
        }
    }
}

static void conv_dual(float* out, const float* base,
                      const float* X1, int C1,
                      const float* X2, int C2,
                      const float* wp,
                      const float* B1, const float* B2,
                      int Cout, float scale, int relu)
{
    dim3 g(HWSZ / CTA_N, Cout / CTA_M, BATCH);
    conv_mma<<<g, 128>>>(out, base, X1, C1, X2, C2, wp, B1, B2,
                         Cout, scale, relu);
}

// ---------------------------------------------------------------------------
extern "C" void kernel_launch(void* const* d_in, const int* in_sizes, int n_in,
                              void* d_out, int out_size)
{
    const float* img_in  = (const float*)d_in[0];
    const float* tf      = (const float*)d_in[1];
    const float* rw1     = (const float*)d_in[2];
    const float* rb1     = (const float*)d_in[3];
    const float* rw2     = (const float*)d_in[4];
    const float* rb2     = (const float*)d_in[5];
    const float* dmc_w   = (const float*)d_in[6];
    const float* dmc_b   = (const float*)d_in[7];
    const float* imc_w01 = (const float*)d_in[8];
    const float* imc_b01 = (const float*)d_in[9];
    const float* imc_w23 = (const float*)d_in[10];
    const float* imc_b23 = (const float*)d_in[11];
    const float* rmc_w01 = (const float*)d_in[12];
    const float* rmc_b01 = (const float*)d_in[13];
    const float* rmc_w23 = (const float*)d_in[14];
    const float* rmc_b23 = (const float*)d_in[15];
    const float* emb_w1  = (const float*)d_in[16];
    const float* emb_b1  = (const float*)d_in[17];
    const float* emb_w2  = (const float*)d_in[18];
    const float* emb_b2  = (const float*)d_in[19];
    const int*   bbox    = (const int*)d_in[20];
    float* out = (float*)d_out;

    float *depA, *depB, *imgA, *relA, *relB, *hmid, *relmap, *wpk;
    cudaGetSymbolAddress((void**)&depA, g_depA);
    cudaGetSymbolAddress((void**)&depB, g_depB);
    cudaGetSymbolAddress((void**)&imgA, g_imgA);
    cudaGetSymbolAddress((void**)&relA, g_relA);
    cudaGetSymbolAddress((void**)&relB, g_relB);
    cudaGetSymbolAddress((void**)&hmid, g_hmid);
    cudaGetSymbolAddress((void**)&relmap, g_relmap);
    cudaGetSymbolAddress((void**)&wpk, g_wpack);

    const size_t WB = (size_t)2 * CH * CH * 9;
    // 0) pack + convert weights for all 6 convs
    pack_kernel<<<512, 256>>>(wpk + WP1, dmc_w + 0 * WB, 1152,
                              dmc_w + 2 * WB, 1152, 256);
    pack_kernel<<<512, 256>>>(wpk + WP2, imc_w01, 2304, imc_w23, 1152, 128);
    pack_kernel<<<512, 256>>>(wpk + WP3, rmc_w01, 2304, rmc_w23, 1152, 128);
    pack_kernel<<<512, 256>>>(wpk + WP4, dmc_w + 1 * WB, 1152,
                              dmc_w + 3 * WB, 1152, 256);
    pack_kernel<<<512, 256>>>(wpk + WP5, emb_w1, 2304, (const float*)0, 0, 128);
    pack_kernel<<<512, 256>>>(wpk + WP6, emb_w2, 1152, (const float*)0, 0, 128);

    // 1) rel embedding: two channel matmuls
    mm_kernel<<<dim3(CH, BATCH), NN>>>(tf,   rw1, rb1, hmid,   CINR, 1);
    mm_kernel<<<dim3(CH, BATCH), NN>>>(hmid, rw2, rb2, relmap, CH,   0);

    // 2) scatter interpolated rows into rel map (writes every element)
    scatter_kernel<<<dim3(HH, BATCH, 2), 64>>>(relmap, bbox, relA);

    // 3) dep = concat(img, rel)
    for (int b = 0; b < BATCH; ++b) {
        cudaMemcpyAsync(depA + ((size_t)b * 2 * CH) * HWSZ,
                        img_in + (size_t)b * CH * HWSZ,
                        sizeof(float) * CH * HWSZ, cudaMemcpyDeviceToDevice);
        cudaMemcpyAsync(depA + ((size_t)b * 2 * CH + CH) * HWSZ,
                        relA + (size_t)b * CH * HWSZ,
                        sizeof(float) * CH * HWSZ, cudaMemcpyDeviceToDevice);
    }

    // 4) TriGraph iteration 0
    conv_dual(depB, depA, img_in, CH, relA, CH, wpk + WP1,
              dmc_b + 0 * 2 * CH, dmc_b + 2 * 2 * CH, 2 * CH, 0.5f, 1);
    conv_dual(imgA, img_in, depA, 2 * CH, relA, CH, wpk + WP2,
              imc_b01, imc_b23, CH, 0.5f, 1);
    conv_dual(relB, relA, depA, 2 * CH, img_in, CH, wpk + WP3,
              rmc_b01, rmc_b23, CH, 0.5f, 1);

    // 5) TriGraph iteration 1: only dep feeds the output
    conv_dual(depA, depB, imgA, CH, relB, CH, wpk + WP4,
              dmc_b + 1 * 2 * CH, dmc_b + 3 * 2 * CH, 2 * CH, 0.5f, 1);

    // 6) final embedding
    conv_dual(relA, nullptr, depA, 2 * CH, nullptr, 0, wpk + WP5,
              emb_b1, nullptr, CH, 1.f, 1);
    conv_dual(out, nullptr, relA, CH, nullptr, 0, wpk + WP6,
              emb_b2, nullptr, CH, 1.f, 0);
}